// round 5
// baseline (speedup 1.0000x reference)
#include <cuda_runtime.h>
#include <math.h>

// Problem dims
#define Vn 8000
#define Bn 64
#define Tn 256
#define Rn 1024
#define Un 512
#define Sn 1024
#define NROWS (Bn * Tn)  // 16384

// ---------------- device scratch (static globals; no runtime allocation) ----
__device__ float g_states[Tn * Bn * Rn];   // [t][b][r]  64 MB
__device__ float g_tmpA[Bn * Rn];
__device__ float g_tmpB[Bn * Rn];
__device__ float g_zero[Bn * Rn];
__device__ float g_outputs[NROWS * Un];    // 32 MB
__device__ float g_slog[NROWS * Sn];       // 64 MB
__device__ float g_tlog[NROWS];
__device__ float g_Ws[Sn * Un];            // gathered sampled softmax_w rows
__device__ float g_svec[Sn];               // softmax_b[sid] - log(sampled_counts)
__device__ int   g_sid[Sn];

// ---------------- helpers ---------------------------------------------------
__device__ __forceinline__ unsigned to_tf32(float x) {
    unsigned r;
    asm("cvt.rna.tf32.f32 %0, %1;" : "=r"(r) : "f"(x));
    return r;
}

__device__ __forceinline__ void mma8(float c[4],
                                     unsigned a0, unsigned a1, unsigned a2, unsigned a3,
                                     unsigned b0, unsigned b1) {
    asm volatile(
        "mma.sync.aligned.m16n8k8.row.col.f32.tf32.tf32.f32 "
        "{%0,%1,%2,%3},{%4,%5,%6,%7},{%8,%9},{%0,%1,%2,%3};"
        : "+f"(c[0]), "+f"(c[1]), "+f"(c[2]), "+f"(c[3])
        : "r"(a0), "r"(a1), "r"(a2), "r"(a3), "r"(b0), "r"(b1));
}

// ---------------- init: zero out, zero state0, gather sampled rows ----------
__global__ void __launch_bounds__(256) init_kernel(
    const int* __restrict__ sampled, const float* __restrict__ scnt,
    const float* __restrict__ sw, const float* __restrict__ sb,
    float* __restrict__ out)
{
    int gt = blockIdx.x * blockDim.x + threadIdx.x;
    int stride = gridDim.x * blockDim.x;
    if (gt == 0) out[0] = 0.0f;
    for (int i = gt; i < Bn * Rn; i += stride) g_zero[i] = 0.0f;
    for (int j = gt; j < Sn; j += stride) {
        int id = sampled[j];
        g_sid[j] = id;
        g_svec[j] = sb[id] - logf(scnt[j]);
    }
    for (int i = gt; i < Sn * Un; i += stride)
        g_Ws[i] = sw[(size_t)sampled[i >> 9] * Un + (i & 511)];
}

// ---------------- highway phase: dual GEMM (h,t) + gate epilogue ------------
// grid 32 CTAs, 256 threads. CTA c handles new-state cols [c*32, c*32+32).
// Warp tile: 16 rows x 16 cols for BOTH h and t (2 n8 tiles each).
__global__ void __launch_bounds__(256) highway_phase(
    const float* __restrict__ src, float* __restrict__ dst,
    const float* __restrict__ Wh, const float* __restrict__ Wt,
    const float* __restrict__ bh, const float* __restrict__ bt,
    const float* __restrict__ emb, const int* __restrict__ inp,
    int step, int K)
{
    __shared__ float catS[64][33];
    __shared__ float whS[32][33];
    __shared__ float wtS[32][33];

    const int tid = threadIdx.x;
    const int warp = tid >> 5, lane = tid & 31;
    const int g = lane >> 2, tig = lane & 3;
    const int rbase = (warp >> 1) * 16;
    const int cbase = (warp & 1) * 16;
    const int jbase = blockIdx.x * 32;

    float hc[2][4] = {{0.f,0.f,0.f,0.f},{0.f,0.f,0.f,0.f}};
    float tc[2][4] = {{0.f,0.f,0.f,0.f},{0.f,0.f,0.f,0.f}};

    for (int t0 = 0; t0 < K; t0 += 32) {
        // stage cat tile [64 rows(b)][32 k]
        #pragma unroll
        for (int r = 0; r < 2; r++) {
            int v = r * 256 + tid;      // 0..511
            int b = v >> 3, q = v & 7;
            int kg = t0 + q * 4;
            const float* p;
            if (emb != nullptr && kg < Un) {
                int tok = inp[b * Tn + step];
                p = emb + (size_t)tok * Un + kg;
            } else {
                int off = (emb != nullptr) ? (kg - Un) : kg;
                p = src + b * Rn + off;
            }
            float4 f = *(const float4*)p;
            catS[b][q*4+0] = __uint_as_float(to_tf32(f.x));
            catS[b][q*4+1] = __uint_as_float(to_tf32(f.y));
            catS[b][q*4+2] = __uint_as_float(to_tf32(f.z));
            catS[b][q*4+3] = __uint_as_float(to_tf32(f.w));
        }
        // stage weight tiles [32 k][32 j] — one float4 per thread per matrix
        {
            int kk = tid >> 3, q = tid & 7;
            float4 fh = *(const float4*)(Wh + (size_t)(t0 + kk) * Rn + jbase + q * 4);
            whS[kk][q*4+0] = __uint_as_float(to_tf32(fh.x));
            whS[kk][q*4+1] = __uint_as_float(to_tf32(fh.y));
            whS[kk][q*4+2] = __uint_as_float(to_tf32(fh.z));
            whS[kk][q*4+3] = __uint_as_float(to_tf32(fh.w));
            float4 ft = *(const float4*)(Wt + (size_t)(t0 + kk) * Rn + jbase + q * 4);
            wtS[kk][q*4+0] = __uint_as_float(to_tf32(ft.x));
            wtS[kk][q*4+1] = __uint_as_float(to_tf32(ft.y));
            wtS[kk][q*4+2] = __uint_as_float(to_tf32(ft.z));
            wtS[kk][q*4+3] = __uint_as_float(to_tf32(ft.w));
        }
        __syncthreads();

        #pragma unroll
        for (int k8 = 0; k8 < 32; k8 += 8) {
            unsigned a0 = __float_as_uint(catS[rbase + g    ][k8 + tig    ]);
            unsigned a1 = __float_as_uint(catS[rbase + g + 8][k8 + tig    ]);
            unsigned a2 = __float_as_uint(catS[rbase + g    ][k8 + tig + 4]);
            unsigned a3 = __float_as_uint(catS[rbase + g + 8][k8 + tig + 4]);
            #pragma unroll
            for (int nt = 0; nt < 2; nt++) {
                int j = cbase + nt * 8 + g;
                unsigned hb0 = __float_as_uint(whS[k8 + tig    ][j]);
                unsigned hb1 = __float_as_uint(whS[k8 + tig + 4][j]);
                mma8(hc[nt], a0, a1, a2, a3, hb0, hb1);
                unsigned tb0 = __float_as_uint(wtS[k8 + tig    ][j]);
                unsigned tb1 = __float_as_uint(wtS[k8 + tig + 4][j]);
                mma8(tc[nt], a0, a1, a2, a3, tb0, tb1);
            }
        }
        __syncthreads();
    }

    // highway epilogue: new = (tanh(h) - s) * sigmoid(t) + s
    #pragma unroll
    for (int nt = 0; nt < 2; nt++) {
        #pragma unroll
        for (int i = 0; i < 4; i++) {
            int b = rbase + g + ((i >= 2) ? 8 : 0);
            int j = jbase + cbase + nt * 8 + tig * 2 + (i & 1);
            float hl = hc[nt][i] + bh[j];
            float tl = tc[nt][i] + bt[j];
            float s  = src[b * Rn + j];
            float tg = 1.0f / (1.0f + __expf(-tl));
            float hv = tanhf(hl);
            dst[b * Rn + j] = (hv - s) * tg + s;
        }
    }
}

// ---------------- projection: outputs[m][u] = states . Wp + bp --------------
// grid (256, 8): CTA tile 64(m) x 64(n), K = 1024. Warp tile 16x32 (4 n8).
__global__ void __launch_bounds__(256) proj_kernel(
    const float* __restrict__ Wp, const float* __restrict__ bp)
{
    __shared__ float AS[64][33];
    __shared__ float BS[32][65];

    const int tid = threadIdx.x;
    const int warp = tid >> 5, lane = tid & 31;
    const int g = lane >> 2, tig = lane & 3;
    const int rbase = (warp >> 1) * 16;
    const int cbase = (warp & 1) * 32;
    const int m0 = blockIdx.x * 64, jb = blockIdx.y * 64;

    float c[4][4] = {{0}};
    #pragma unroll
    for (int nt = 0; nt < 4; nt++)
        #pragma unroll
        for (int i = 0; i < 4; i++) c[nt][i] = 0.f;

    for (int t0 = 0; t0 < Rn; t0 += 32) {
        #pragma unroll
        for (int r = 0; r < 2; r++) {
            int v = r * 256 + tid;          // 0..511
            int row = v >> 3, q = v & 7;
            int m = m0 + row;               // m = b*T + t
            const float* p = g_states + (size_t)(m & (Tn - 1)) * (Bn * Rn)
                                      + (size_t)(m >> 8) * Rn + t0 + q * 4;
            float4 f = *(const float4*)p;
            AS[row][q*4+0] = __uint_as_float(to_tf32(f.x));
            AS[row][q*4+1] = __uint_as_float(to_tf32(f.y));
            AS[row][q*4+2] = __uint_as_float(to_tf32(f.z));
            AS[row][q*4+3] = __uint_as_float(to_tf32(f.w));
        }
        #pragma unroll
        for (int r = 0; r < 2; r++) {
            int v = r * 256 + tid;          // 0..511 float4s
            int kk = v >> 4, jq = v & 15;
            float4 f = *(const float4*)(Wp + (size_t)(t0 + kk) * Un + jb + jq * 4);
            BS[kk][jq*4+0] = __uint_as_float(to_tf32(f.x));
            BS[kk][jq*4+1] = __uint_as_float(to_tf32(f.y));
            BS[kk][jq*4+2] = __uint_as_float(to_tf32(f.z));
            BS[kk][jq*4+3] = __uint_as_float(to_tf32(f.w));
        }
        __syncthreads();

        #pragma unroll
        for (int k8 = 0; k8 < 32; k8 += 8) {
            unsigned a0 = __float_as_uint(AS[rbase + g    ][k8 + tig    ]);
            unsigned a1 = __float_as_uint(AS[rbase + g + 8][k8 + tig    ]);
            unsigned a2 = __float_as_uint(AS[rbase + g    ][k8 + tig + 4]);
            unsigned a3 = __float_as_uint(AS[rbase + g + 8][k8 + tig + 4]);
            #pragma unroll
            for (int nt = 0; nt < 4; nt++) {
                int j = cbase + nt * 8 + g;
                unsigned b0 = __float_as_uint(BS[k8 + tig    ][j]);
                unsigned b1 = __float_as_uint(BS[k8 + tig + 4][j]);
                mma8(c[nt], a0, a1, a2, a3, b0, b1);
            }
        }
        __syncthreads();
    }

    #pragma unroll
    for (int nt = 0; nt < 4; nt++) {
        #pragma unroll
        for (int i = 0; i < 4; i++) {
            int m = m0 + rbase + g + ((i >= 2) ? 8 : 0);
            int j = jb + cbase + nt * 8 + tig * 2 + (i & 1);
            g_outputs[(size_t)m * Un + j] = c[nt][i] + bp[j];
        }
    }
}

// ---------------- sampled logits: outputs @ Ws^T + svec, hit mask ----------
// grid (256, 16): CTA tile 64(m) x 64(n), K = 512.
__global__ void __launch_bounds__(256) slog_kernel(const int* __restrict__ labels)
{
    __shared__ float AS[64][33];
    __shared__ float BS[32][65];

    const int tid = threadIdx.x;
    const int warp = tid >> 5, lane = tid & 31;
    const int g = lane >> 2, tig = lane & 3;
    const int rbase = (warp >> 1) * 16;
    const int cbase = (warp & 1) * 32;
    const int m0 = blockIdx.x * 64, jb = blockIdx.y * 64;

    float c[4][4];
    #pragma unroll
    for (int nt = 0; nt < 4; nt++)
        #pragma unroll
        for (int i = 0; i < 4; i++) c[nt][i] = 0.f;

    for (int t0 = 0; t0 < Un; t0 += 32) {
        #pragma unroll
        for (int r = 0; r < 2; r++) {
            int v = r * 256 + tid;
            int row = v >> 3, q = v & 7;
            const float* p = g_outputs + (size_t)(m0 + row) * Un + t0 + q * 4;
            float4 f = *(const float4*)p;
            AS[row][q*4+0] = __uint_as_float(to_tf32(f.x));
            AS[row][q*4+1] = __uint_as_float(to_tf32(f.y));
            AS[row][q*4+2] = __uint_as_float(to_tf32(f.z));
            AS[row][q*4+3] = __uint_as_float(to_tf32(f.w));
        }
        // B = Ws[j][k] (row-major n x k == col-major k x n): transpose into BS[k][j]
        #pragma unroll
        for (int r = 0; r < 2; r++) {
            int v = r * 256 + tid;          // 0..511
            int j = v >> 3, q = v & 7;
            float4 f = *(const float4*)(g_Ws + (size_t)(jb + j) * Un + t0 + q * 4);
            BS[q*4+0][j] = __uint_as_float(to_tf32(f.x));
            BS[q*4+1][j] = __uint_as_float(to_tf32(f.y));
            BS[q*4+2][j] = __uint_as_float(to_tf32(f.z));
            BS[q*4+3][j] = __uint_as_float(to_tf32(f.w));
        }
        __syncthreads();

        #pragma unroll
        for (int k8 = 0; k8 < 32; k8 += 8) {
            unsigned a0 = __float_as_uint(AS[rbase + g    ][k8 + tig    ]);
            unsigned a1 = __float_as_uint(AS[rbase + g + 8][k8 + tig    ]);
            unsigned a2 = __float_as_uint(AS[rbase + g    ][k8 + tig + 4]);
            unsigned a3 = __float_as_uint(AS[rbase + g + 8][k8 + tig + 4]);
            #pragma unroll
            for (int nt = 0; nt < 4; nt++) {
                int j = cbase + nt * 8 + g;
                unsigned b0 = __float_as_uint(BS[k8 + tig    ][j]);
                unsigned b1 = __float_as_uint(BS[k8 + tig + 4][j]);
                mma8(c[nt], a0, a1, a2, a3, b0, b1);
            }
        }
        __syncthreads();
    }

    #pragma unroll
    for (int nt = 0; nt < 4; nt++) {
        #pragma unroll
        for (int i = 0; i < 4; i++) {
            int m = m0 + rbase + g + ((i >= 2) ? 8 : 0);
            int j = jb + cbase + nt * 8 + tig * 2 + (i & 1);
            float v = c[nt][i] + g_svec[j];
            if (labels[m] == g_sid[j]) v -= 1e9f;
            g_slog[(size_t)m * Sn + j] = v;
        }
    }
}

// ---------------- true logits: warp per row ---------------------------------
__global__ void __launch_bounds__(256) tlog_kernel(
    const int* __restrict__ labels, const float* __restrict__ sw,
    const float* __restrict__ sb, const float* __restrict__ tcnt)
{
    int warp = threadIdx.x >> 5, lane = threadIdx.x & 31;
    int n = blockIdx.x * 8 + warp;
    int lab = labels[n];
    const float4* o = (const float4*)(g_outputs + (size_t)n * Un);
    const float4* w = (const float4*)(sw + (size_t)lab * Un);
    float acc = 0.f;
    #pragma unroll
    for (int q = 0; q < 4; q++) {
        float4 a = o[lane + q * 32];
        float4 b = w[lane + q * 32];
        acc += a.x * b.x + a.y * b.y + a.z * b.z + a.w * b.w;
    }
    #pragma unroll
    for (int s = 16; s; s >>= 1) acc += __shfl_xor_sync(0xffffffffu, acc, s);
    if (lane == 0) g_tlog[n] = acc + sb[lab] - logf(tcnt[n]);
}

// ---------------- loss: warp per row, online logsumexp ----------------------
__global__ void __launch_bounds__(256) loss_kernel(float* __restrict__ out)
{
    __shared__ float red[8];
    int warp = threadIdx.x >> 5, lane = threadIdx.x & 31;
    int n = blockIdx.x * 8 + warp;

    float mL = -INFINITY, sL = 0.f;
    const float* row = g_slog + (size_t)n * Sn;
    for (int j = lane; j < Sn; j += 32) {
        float v = row[j];
        if (v > mL) { sL = sL * __expf(mL - v) + 1.f; mL = v; }
        else          sL += __expf(v - mL);
    }
    #pragma unroll
    for (int s = 16; s; s >>= 1) {
        float m2 = __shfl_xor_sync(0xffffffffu, mL, s);
        float s2 = __shfl_xor_sync(0xffffffffu, sL, s);
        float M = fmaxf(mL, m2);
        sL = sL * __expf(mL - M) + s2 * __expf(m2 - M);
        mL = M;
    }
    float z0 = g_tlog[n];
    float M = fmaxf(mL, z0);
    float S = sL * __expf(mL - M) + __expf(z0 - M);
    float loss = (M + logf(S)) - z0;

    if (lane == 0) red[warp] = loss;
    __syncthreads();
    if (threadIdx.x == 0) {
        float t = 0.f;
        #pragma unroll
        for (int i = 0; i < 8; i++) t += red[i];
        atomicAdd(out, t * (1.0f / NROWS));
    }
}

// ---------------- launch ----------------------------------------------------
extern "C" void kernel_launch(void* const* d_in, const int* in_sizes, int n_in,
                              void* d_out, int out_size)
{
    (void)in_sizes; (void)n_in; (void)out_size;

    const int*   input   = (const int*)  d_in[0];
    const int*   targets = (const int*)  d_in[1];
    const int*   sampled = (const int*)  d_in[2];
    const float* tcnt    = (const float*)d_in[3];
    const float* scnt    = (const float*)d_in[4];
    const float* emb     = (const float*)d_in[5];
    const float* Wh0     = (const float*)d_in[6];
    const float* bh0     = (const float*)d_in[7];
    const float* Wt0     = (const float*)d_in[8];
    const float* bt0     = (const float*)d_in[9];
    const float* Wh      = (const float*)d_in[10];
    const float* bh      = (const float*)d_in[11];
    const float* Wt      = (const float*)d_in[12];
    const float* bt      = (const float*)d_in[13];
    const float* Wp      = (const float*)d_in[14];
    const float* bp      = (const float*)d_in[15];
    const float* sw      = (const float*)d_in[16];
    const float* sb      = (const float*)d_in[17];
    float* out = (float*)d_out;

    float *states, *tmpA, *tmpB, *zero;
    cudaGetSymbolAddress((void**)&states, g_states);
    cudaGetSymbolAddress((void**)&tmpA,   g_tmpA);
    cudaGetSymbolAddress((void**)&tmpB,   g_tmpB);
    cudaGetSymbolAddress((void**)&zero,   g_zero);

    init_kernel<<<256, 256>>>(sampled, scnt, sw, sb, out);

    for (int step = 0; step < Tn; step++) {
        const float* src0 = (step == 0) ? zero : (states + (size_t)(step - 1) * Bn * Rn);
        highway_phase<<<32, 256>>>(src0, tmpA, Wh0, Wt0, bh0, bt0,
                                   emb, input, step, Un + Rn);
        highway_phase<<<32, 256>>>(tmpA, tmpB, Wh, Wt, bh, bt,
                                   nullptr, nullptr, 0, Rn);
        highway_phase<<<32, 256>>>(tmpB, states + (size_t)step * Bn * Rn,
                                   Wh + (size_t)Rn * Rn, Wt + (size_t)Rn * Rn,
                                   bh + Rn, bt + Rn,
                                   nullptr, nullptr, 0, Rn);
    }

    proj_kernel<<<dim3(NROWS / 64, Un / 64), 256>>>(Wp, bp);
    slog_kernel<<<dim3(NROWS / 64, Sn / 64), 256>>>(targets);
    tlog_kernel<<<NROWS / 8, 256>>>(targets, sw, sb, tcnt);
    loss_kernel<<<NROWS / 8, 256>>>(out);
}